// round 6
// baseline (speedup 1.0000x reference)
#include <cuda_runtime.h>

#define IMW 512
#define IMH 512
#define NIMG 48          // B*C = 16*3
#define TSZ 32

// Scratch (static __device__ — no allocations allowed)
__device__ float g_tmp[NIMG*IMH*IMW];
__device__ float g_imc[NIMG*IMH*IMW];
__device__ float g_tn [NIMG*TSZ*TSZ];

__device__ __forceinline__ void ffma2(unsigned long long& d,
                                      unsigned long long a,
                                      unsigned long long b) {
    asm("fma.rn.f32x2 %0, %1, %2, %0;" : "+l"(d) : "l"(a), "l"(b));
}

// ---------------------------------------------------------------------------
// K0: template normalize: tn = (t - mean(t)) / ||t - mean(t)||  per (b,c)
// ---------------------------------------------------------------------------
__global__ void k_tnorm(const float* __restrict__ t) {
    __shared__ float red[256];
    int img = blockIdx.x;
    int tid = threadIdx.x;
    const float4* tp = (const float4*)(t + img * 1024);
    float4 v = tp[tid];
    red[tid] = v.x + v.y + v.z + v.w;
    __syncthreads();
    for (int o = 128; o > 0; o >>= 1) {
        if (tid < o) red[tid] += red[tid + o];
        __syncthreads();
    }
    float mean = red[0] * (1.0f / 1024.0f);
    __syncthreads();
    float cx = v.x - mean, cy = v.y - mean, cz = v.z - mean, cw = v.w - mean;
    red[tid] = cx*cx + cy*cy + cz*cz + cw*cw;
    __syncthreads();
    for (int o = 128; o > 0; o >>= 1) {
        if (tid < o) red[tid] += red[tid + o];
        __syncthreads();
    }
    float inv = 1.0f / sqrtf(red[0]);
    float4* outp = (float4*)(g_tn + img * 1024);
    outp[tid] = make_float4(cx*inv, cy*inv, cz*inv, cw*inv);
}

// ---------------------------------------------------------------------------
// K1/K3: horizontal 32-wide box sum (offsets -15..+16), zero padded.
// Running-sum, bank-skewed padded smem addressing HP(c)=c+c/16.
// ---------------------------------------------------------------------------
#define HP(c) ((c) + ((c) >> 4))

template<int SQ>
__global__ __launch_bounds__(256) void k_hbox(const float* __restrict__ im) {
    __shared__ float s [8][578];
    __shared__ float so[8][544];
    int tid = threadIdx.x;
    int row0 = blockIdx.x * 8;
    const float* src = SQ ? (const float*)g_imc : im;

    for (int i = tid; i < 8 * 544; i += 256) {
        int r = i / 544, c = i % 544;
        float v = 0.0f;
        if (c >= 16 && c < 528) {
            v = src[(row0 + r) * IMW + (c - 16)];
            if (SQ) v *= v;
        }
        s[r][HP(c)] = v;
    }
    __syncthreads();

    int w = tid >> 5, lane = tid & 31;
    int x0 = lane * 16;
    float sum = 0.0f;
    #pragma unroll
    for (int j = 0; j < 32; j++) sum += s[w][HP(x0 + 1 + j)];
    so[w][HP(x0)] = sum;
    #pragma unroll
    for (int i = 1; i < 16; i++) {
        sum += s[w][HP(x0 + 32 + i)] - s[w][HP(x0 + i)];
        so[w][HP(x0 + i)] = sum;
    }
    __syncthreads();

    for (int i = tid; i < 8 * 512; i += 256) {
        int r = i >> 9, c = i & 511;
        g_tmp[(row0 + r) * IMW + c] = so[r][HP(c)];
    }
}

// ---------------------------------------------------------------------------
// K2/K4: vertical 32-tall box sum (running sum per column segment).
// FINAL=0: g_imc = im - S1/1024
// FINAL=1: g_imc = g_imc / sqrt(max(S2, 0))
// ---------------------------------------------------------------------------
template<int FINAL>
__global__ __launch_bounds__(256) void k_vbox(const float* __restrict__ im) {
    int idx = blockIdx.x * 256 + threadIdx.x;
    int x   = idx % IMW;
    int img = (idx / IMW) % NIMG;
    int seg = idx / (IMW * NIMG);
    int y0  = seg * 128;

    const float* col = g_tmp + img * IMH * IMW + x;
    float s = 0.0f;
    #pragma unroll
    for (int j = y0 - 16; j < y0 + 16; j++)
        if (j >= 0) s += col[j * IMW];

    const float* base = (FINAL ? (const float*)g_imc : im) + img * IMH * IMW + x;
    float* outp = g_imc + img * IMH * IMW + x;

    for (int y = y0; y < y0 + 128; y++) {
        if (y + 16 < IMH) s += col[(y + 16) * IMW];
        if (y - 16 >= 0)  s -= col[(y - 16) * IMW];
        float v = base[y * IMW];
        outp[y * IMW] = FINAL ? v / sqrtf(fmaxf(s, 0.0f))
                              : v - s * (1.0f / 1024.0f);
    }
}

// ---------------------------------------------------------------------------
// K5: direct 32x32 correlation via packed f32x2 FMA, rolling w-window.
// Per thread: 8 outputs (x octet). Packed accumulators accP[dx]:
//   even dx=2d:   accP += wE[k+d] x tE[k],  k=0..15
//   odd  dx=2d+1: accP += wE[i+d] x tO[i],  i=0..16 (tO zero-padded shift)
// Both passes fused over k2=0..7: each k2 consumes w-pairs 2k2..2k2+4 for
// BOTH even and odd — rolling 8-slot register window (slide 2/iter, loads
// land 1 iteration ahead of use). Live regs ~60 -> >=2 blocks/SM.
// ---------------------------------------------------------------------------
#define CTX 64
#define CTY 32
#define INROWS 63          // CTY + 31
#define INCOLS 95          // CTX + 31
#define INS 100            // smem row stride (400B, 16B-aligned, bank-skewed)

__global__ __launch_bounds__(256, 2) void k_conv(float* __restrict__ out) {
    __shared__ __align__(16) float s_in[INROWS * INS];   // 25200 B
    __shared__ __align__(16) float s_tE[32 * 32];        // 4096 B
    __shared__ __align__(16) float s_tO[32 * 36];        // 4608 B

    int img = blockIdx.z;
    int X0 = blockIdx.x * CTX;
    int Y0 = blockIdx.y * CTY;
    int tid = threadIdx.x;

    const float* T = g_tn + img * 1024;
    ((float4*)s_tE)[tid] = ((const float4*)T)[tid];
    for (int e = tid; e < 32 * 17; e += 256) {
        int u = e / 17, i = e % 17;
        float lo = (i == 0)  ? 0.0f : T[u * 32 + 2 * i - 1];
        float hi = (i == 16) ? 0.0f : T[u * 32 + 2 * i];
        s_tO[u * 36 + 2 * i]     = lo;
        s_tO[u * 36 + 2 * i + 1] = hi;
    }

    // input tile rows [Y0-15, Y0+47], cols [X0-15, X0+79]; zero-fill the
    // whole INS-wide row (packed path multiplies pad cols by 0)
    const float* A = g_imc + img * IMH * IMW;
    for (int i = tid; i < INROWS * INS; i += 256) {
        int ly = i / INS, lx = i % INS;
        int gy = Y0 - 15 + ly, gx = X0 - 15 + lx;
        float v = 0.0f;
        if (lx < INCOLS && gy >= 0 && gy < IMH && gx >= 0 && gx < IMW)
            v = A[gy * IMW + gx];
        s_in[i] = v;
    }
    __syncthreads();

    int r  = tid & 31;          // output row in tile
    int ox = (tid >> 5) * 8;    // output x octet base

    unsigned long long accP[8];
    #pragma unroll
    for (int k = 0; k < 8; k++) accP[k] = 0ull;

    #pragma unroll 1
    for (int u = 0; u < 32; u++) {
        const ulonglong2* wb = (const ulonglong2*)&s_in[(r + u) * INS + ox];
        const ulonglong2* te = (const ulonglong2*)&s_tE[u * 32];
        const ulonglong2* to = (const ulonglong2*)&s_tO[u * 36];

        // preload w pairs 0..5 into slots 0..5
        unsigned long long wreg[8];
        {
            ulonglong2 q0 = wb[0], q1 = wb[1], q2 = wb[2];
            wreg[0] = q0.x; wreg[1] = q0.y;
            wreg[2] = q1.x; wreg[3] = q1.y;
            wreg[4] = q2.x; wreg[5] = q2.y;
        }

        #pragma unroll
        for (int k2 = 0; k2 < 8; k2++) {
            // prefetch pairs 2k2+6, 2k2+7 (slots free since iter k2-1)
            if (k2 < 7) {
                ulonglong2 q = wb[k2 + 3];
                wreg[(2 * k2 + 6) & 7] = q.x;
                wreg[(2 * k2 + 7) & 7] = q.y;
            }
            ulonglong2 tqe = te[k2];
            ulonglong2 tqo = to[k2];
            #pragma unroll
            for (int d = 0; d < 4; d++) {
                unsigned long long w0 = wreg[(2 * k2 + d) & 7];
                ffma2(accP[2 * d],     w0, tqe.x);
                ffma2(accP[2 * d + 1], w0, tqo.x);
            }
            #pragma unroll
            for (int d = 0; d < 4; d++) {
                unsigned long long w1 = wreg[(2 * k2 + 1 + d) & 7];
                ffma2(accP[2 * d],     w1, tqe.y);
                ffma2(accP[2 * d + 1], w1, tqo.y);
            }
        }
        // odd tail i=16: pairs 16..19 live in slots 0..3
        unsigned long long tql = ((const unsigned long long*)&s_tO[u * 36])[16];
        #pragma unroll
        for (int d = 0; d < 4; d++)
            ffma2(accP[2 * d + 1], wreg[d], tql);
    }

    float res[8];
    #pragma unroll
    for (int dx = 0; dx < 8; dx++) {
        float2 p = *(float2*)&accP[dx];
        res[dx] = p.x + p.y;
    }

    float* o = out + ((size_t)(img * IMH + Y0 + r)) * IMW + X0 + ox;
    ((float4*)o)[0] = make_float4(res[0], res[1], res[2], res[3]);
    ((float4*)o)[1] = make_float4(res[4], res[5], res[6], res[7]);
}

// ---------------------------------------------------------------------------
extern "C" void kernel_launch(void* const* d_in, const int* in_sizes, int n_in,
                              void* d_out, int out_size) {
    const float* im   = (const float*)d_in[0];  // (16,3,512,512) f32
    const float* tmpl = (const float*)d_in[1];  // (16,3,32,32)  f32
    float* out = (float*)d_out;                 // (16,3,512,512) f32

    k_tnorm<<<NIMG, 256>>>(tmpl);
    k_hbox<0><<<NIMG * IMH / 8, 256>>>(im);                 // S1 horizontal
    k_vbox<0><<<NIMG * IMW * 4 / 256, 256>>>(im);           // im_c
    k_hbox<1><<<NIMG * IMH / 8, 256>>>(im);                 // S2 horizontal (imc^2)
    k_vbox<1><<<NIMG * IMW * 4 / 256, 256>>>(im);           // a = imc/energy
    k_conv<<<dim3(IMW / CTX, IMH / CTY, NIMG), 256>>>(out); // correlation
}

// round 7
// speedup vs baseline: 1.0036x; 1.0036x over previous
#include <cuda_runtime.h>

#define IMW 512
#define IMH 512
#define NIMG 48          // B*C = 16*3
#define TSZ 32

// Scratch (static __device__ — no allocations allowed)
__device__ float g_tmp[NIMG*IMH*IMW];
__device__ float g_imc[NIMG*IMH*IMW];
__device__ float g_tn [NIMG*TSZ*TSZ];

__device__ __forceinline__ void ffma2(unsigned long long& d,
                                      unsigned long long a,
                                      unsigned long long b) {
    asm("fma.rn.f32x2 %0, %1, %2, %0;" : "+l"(d) : "l"(a), "l"(b));
}

// ---------------------------------------------------------------------------
// K0: template normalize: tn = (t - mean(t)) / ||t - mean(t)||  per (b,c)
// ---------------------------------------------------------------------------
__global__ void k_tnorm(const float* __restrict__ t) {
    __shared__ float red[256];
    int img = blockIdx.x;
    int tid = threadIdx.x;
    const float4* tp = (const float4*)(t + img * 1024);
    float4 v = tp[tid];
    red[tid] = v.x + v.y + v.z + v.w;
    __syncthreads();
    for (int o = 128; o > 0; o >>= 1) {
        if (tid < o) red[tid] += red[tid + o];
        __syncthreads();
    }
    float mean = red[0] * (1.0f / 1024.0f);
    __syncthreads();
    float cx = v.x - mean, cy = v.y - mean, cz = v.z - mean, cw = v.w - mean;
    red[tid] = cx*cx + cy*cy + cz*cz + cw*cw;
    __syncthreads();
    for (int o = 128; o > 0; o >>= 1) {
        if (tid < o) red[tid] += red[tid + o];
        __syncthreads();
    }
    float inv = 1.0f / sqrtf(red[0]);
    float4* outp = (float4*)(g_tn + img * 1024);
    outp[tid] = make_float4(cx*inv, cy*inv, cz*inv, cw*inv);
}

// ---------------------------------------------------------------------------
// K1/K3: horizontal 32-wide box sum (offsets -15..+16), zero padded.
// Running-sum, bank-skewed padded smem addressing HP(c)=c+c/16.
// ---------------------------------------------------------------------------
#define HP(c) ((c) + ((c) >> 4))

template<int SQ>
__global__ __launch_bounds__(256) void k_hbox(const float* __restrict__ im) {
    __shared__ float s [8][578];
    __shared__ float so[8][544];
    int tid = threadIdx.x;
    int row0 = blockIdx.x * 8;
    const float* src = SQ ? (const float*)g_imc : im;

    for (int i = tid; i < 8 * 544; i += 256) {
        int r = i / 544, c = i % 544;
        float v = 0.0f;
        if (c >= 16 && c < 528) {
            v = src[(row0 + r) * IMW + (c - 16)];
            if (SQ) v *= v;
        }
        s[r][HP(c)] = v;
    }
    __syncthreads();

    int w = tid >> 5, lane = tid & 31;
    int x0 = lane * 16;
    float sum = 0.0f;
    #pragma unroll
    for (int j = 0; j < 32; j++) sum += s[w][HP(x0 + 1 + j)];
    so[w][HP(x0)] = sum;
    #pragma unroll
    for (int i = 1; i < 16; i++) {
        sum += s[w][HP(x0 + 32 + i)] - s[w][HP(x0 + i)];
        so[w][HP(x0 + i)] = sum;
    }
    __syncthreads();

    for (int i = tid; i < 8 * 512; i += 256) {
        int r = i >> 9, c = i & 511;
        g_tmp[(row0 + r) * IMW + c] = so[r][HP(c)];
    }
}

// ---------------------------------------------------------------------------
// K2/K4: vertical 32-tall box sum (running sum per column segment).
// FINAL=0: g_imc = im - S1/1024
// FINAL=1: g_imc = g_imc / sqrt(max(S2, 0))
// ---------------------------------------------------------------------------
template<int FINAL>
__global__ __launch_bounds__(256) void k_vbox(const float* __restrict__ im) {
    int idx = blockIdx.x * 256 + threadIdx.x;
    int x   = idx % IMW;
    int img = (idx / IMW) % NIMG;
    int seg = idx / (IMW * NIMG);
    int y0  = seg * 128;

    const float* col = g_tmp + img * IMH * IMW + x;
    float s = 0.0f;
    #pragma unroll
    for (int j = y0 - 16; j < y0 + 16; j++)
        if (j >= 0) s += col[j * IMW];

    const float* base = (FINAL ? (const float*)g_imc : im) + img * IMH * IMW + x;
    float* outp = g_imc + img * IMH * IMW + x;

    for (int y = y0; y < y0 + 128; y++) {
        if (y + 16 < IMH) s += col[(y + 16) * IMW];
        if (y - 16 >= 0)  s -= col[(y - 16) * IMW];
        float v = base[y * IMW];
        outp[y * IMW] = FINAL ? v / sqrtf(fmaxf(s, 0.0f))
                              : v - s * (1.0f / 1024.0f);
    }
}

// ---------------------------------------------------------------------------
// K5: direct 32x32 correlation via packed f32x2 FMA, rolling w-window.
// Per thread: 8 outputs (x octet). Packed accumulators accP[dx]:
//   even dx=2d:   accP += wE[k+d] x tE[k],  k=0..15
//   odd  dx=2d+1: accP += wE[i+d] x tO[i],  i=0..16 (tO zero-padded shift)
// Both passes fused over k2=0..7: each k2 consumes w-pairs 2k2..2k2+4 for
// BOTH even and odd — rolling 8-slot register window (slide 2/iter, loads
// land 1 iteration ahead of use). Live regs ~60 -> >=2 blocks/SM.
// ---------------------------------------------------------------------------
#define CTX 64
#define CTY 32
#define INROWS 63          // CTY + 31
#define INCOLS 95          // CTX + 31
#define INS 100            // smem row stride (400B, 16B-aligned, bank-skewed)

__global__ __launch_bounds__(256, 2) void k_conv(float* __restrict__ out) {
    __shared__ __align__(16) float s_in[INROWS * INS];   // 25200 B
    __shared__ __align__(16) float s_tE[32 * 32];        // 4096 B
    __shared__ __align__(16) float s_tO[32 * 36];        // 4608 B

    int img = blockIdx.z;
    int X0 = blockIdx.x * CTX;
    int Y0 = blockIdx.y * CTY;
    int tid = threadIdx.x;

    const float* T = g_tn + img * 1024;
    ((float4*)s_tE)[tid] = ((const float4*)T)[tid];
    for (int e = tid; e < 32 * 17; e += 256) {
        int u = e / 17, i = e % 17;
        float lo = (i == 0)  ? 0.0f : T[u * 32 + 2 * i - 1];
        float hi = (i == 16) ? 0.0f : T[u * 32 + 2 * i];
        s_tO[u * 36 + 2 * i]     = lo;
        s_tO[u * 36 + 2 * i + 1] = hi;
    }

    // input tile rows [Y0-15, Y0+47], cols [X0-15, X0+79]; zero-fill the
    // whole INS-wide row (packed path multiplies pad cols by 0)
    const float* A = g_imc + img * IMH * IMW;
    for (int i = tid; i < INROWS * INS; i += 256) {
        int ly = i / INS, lx = i % INS;
        int gy = Y0 - 15 + ly, gx = X0 - 15 + lx;
        float v = 0.0f;
        if (lx < INCOLS && gy >= 0 && gy < IMH && gx >= 0 && gx < IMW)
            v = A[gy * IMW + gx];
        s_in[i] = v;
    }
    __syncthreads();

    int r  = tid & 31;          // output row in tile
    int ox = (tid >> 5) * 8;    // output x octet base

    unsigned long long accP[8];
    #pragma unroll
    for (int k = 0; k < 8; k++) accP[k] = 0ull;

    #pragma unroll 1
    for (int u = 0; u < 32; u++) {
        const ulonglong2* wb = (const ulonglong2*)&s_in[(r + u) * INS + ox];
        const ulonglong2* te = (const ulonglong2*)&s_tE[u * 32];
        const ulonglong2* to = (const ulonglong2*)&s_tO[u * 36];

        // preload w pairs 0..5 into slots 0..5
        unsigned long long wreg[8];
        {
            ulonglong2 q0 = wb[0], q1 = wb[1], q2 = wb[2];
            wreg[0] = q0.x; wreg[1] = q0.y;
            wreg[2] = q1.x; wreg[3] = q1.y;
            wreg[4] = q2.x; wreg[5] = q2.y;
        }

        #pragma unroll
        for (int k2 = 0; k2 < 8; k2++) {
            // prefetch pairs 2k2+6, 2k2+7 (slots free since iter k2-1)
            if (k2 < 7) {
                ulonglong2 q = wb[k2 + 3];
                wreg[(2 * k2 + 6) & 7] = q.x;
                wreg[(2 * k2 + 7) & 7] = q.y;
            }
            ulonglong2 tqe = te[k2];
            ulonglong2 tqo = to[k2];
            #pragma unroll
            for (int d = 0; d < 4; d++) {
                unsigned long long w0 = wreg[(2 * k2 + d) & 7];
                ffma2(accP[2 * d],     w0, tqe.x);
                ffma2(accP[2 * d + 1], w0, tqo.x);
            }
            #pragma unroll
            for (int d = 0; d < 4; d++) {
                unsigned long long w1 = wreg[(2 * k2 + 1 + d) & 7];
                ffma2(accP[2 * d],     w1, tqe.y);
                ffma2(accP[2 * d + 1], w1, tqo.y);
            }
        }
        // odd tail i=16: pairs 16..19 live in slots 0..3
        unsigned long long tql = ((const unsigned long long*)&s_tO[u * 36])[16];
        #pragma unroll
        for (int d = 0; d < 4; d++)
            ffma2(accP[2 * d + 1], wreg[d], tql);
    }

    float res[8];
    #pragma unroll
    for (int dx = 0; dx < 8; dx++) {
        float2 p = *(float2*)&accP[dx];
        res[dx] = p.x + p.y;
    }

    float* o = out + ((size_t)(img * IMH + Y0 + r)) * IMW + X0 + ox;
    ((float4*)o)[0] = make_float4(res[0], res[1], res[2], res[3]);
    ((float4*)o)[1] = make_float4(res[4], res[5], res[6], res[7]);
}

// ---------------------------------------------------------------------------
extern "C" void kernel_launch(void* const* d_in, const int* in_sizes, int n_in,
                              void* d_out, int out_size) {
    const float* im   = (const float*)d_in[0];  // (16,3,512,512) f32
    const float* tmpl = (const float*)d_in[1];  // (16,3,32,32)  f32
    float* out = (float*)d_out;                 // (16,3,512,512) f32

    k_tnorm<<<NIMG, 256>>>(tmpl);
    k_hbox<0><<<NIMG * IMH / 8, 256>>>(im);                 // S1 horizontal
    k_vbox<0><<<NIMG * IMW * 4 / 256, 256>>>(im);           // im_c
    k_hbox<1><<<NIMG * IMH / 8, 256>>>(im);                 // S2 horizontal (imc^2)
    k_vbox<1><<<NIMG * IMW * 4 / 256, 256>>>(im);           // a = imc/energy
    k_conv<<<dim3(IMW / CTX, IMH / CTY, NIMG), 256>>>(out); // correlation
}

// round 15
// speedup vs baseline: 1.2104x; 1.2062x over previous
#include <cuda_runtime.h>
#include <cuda_bf16.h>
#include <cstdint>

#define IMW 512
#define IMH 512
#define NIMG 48          // B*C = 16*3
#define TSZ 32

// Scratch (static __device__ — no allocations allowed)
__device__ float g_tmp[NIMG*IMH*IMW];
__device__ float g_imc[NIMG*IMH*IMW];
__device__ float g_tn [NIMG*TSZ*TSZ];

// ===========================================================================
// K0: template normalize: tn = (t - mean) / ||t - mean||
// ===========================================================================
__global__ void k_tnorm(const float* __restrict__ t) {
    __shared__ float red[256];
    int img = blockIdx.x;
    int tid = threadIdx.x;
    const float4* tp = (const float4*)(t + img * 1024);
    float4 v = tp[tid];
    red[tid] = v.x + v.y + v.z + v.w;
    __syncthreads();
    for (int o = 128; o > 0; o >>= 1) {
        if (tid < o) red[tid] += red[tid + o];
        __syncthreads();
    }
    float mean = red[0] * (1.0f / 1024.0f);
    __syncthreads();
    float cx = v.x - mean, cy = v.y - mean, cz = v.z - mean, cw = v.w - mean;
    red[tid] = cx*cx + cy*cy + cz*cz + cw*cw;
    __syncthreads();
    for (int o = 128; o > 0; o >>= 1) {
        if (tid < o) red[tid] += red[tid + o];
        __syncthreads();
    }
    float inv = 1.0f / sqrtf(red[0]);
    float4* outp = (float4*)(g_tn + img * 1024);
    outp[tid] = make_float4(cx*inv, cy*inv, cz*inv, cw*inv);
}

// ===========================================================================
// K1/K3: horizontal 32-wide box sum (running sum, bank-skewed smem)
// ===========================================================================
#define HP(c) ((c) + ((c) >> 4))

template<int SQ>
__global__ __launch_bounds__(256) void k_hbox(const float* __restrict__ im) {
    __shared__ float s [8][578];
    __shared__ float so[8][544];
    int tid = threadIdx.x;
    int row0 = blockIdx.x * 8;
    const float* src = SQ ? (const float*)g_imc : im;

    for (int i = tid; i < 8 * 544; i += 256) {
        int r = i / 544, c = i % 544;
        float v = 0.0f;
        if (c >= 16 && c < 528) {
            v = src[(row0 + r) * IMW + (c - 16)];
            if (SQ) v *= v;
        }
        s[r][HP(c)] = v;
    }
    __syncthreads();

    int w = tid >> 5, lane = tid & 31;
    int x0 = lane * 16;
    float sum = 0.0f;
    #pragma unroll
    for (int j = 0; j < 32; j++) sum += s[w][HP(x0 + 1 + j)];
    so[w][HP(x0)] = sum;
    #pragma unroll
    for (int i = 1; i < 16; i++) {
        sum += s[w][HP(x0 + 32 + i)] - s[w][HP(x0 + i)];
        so[w][HP(x0 + i)] = sum;
    }
    __syncthreads();

    for (int i = tid; i < 8 * 512; i += 256) {
        int r = i >> 9, c = i & 511;
        g_tmp[(row0 + r) * IMW + c] = so[r][HP(c)];
    }
}

// ===========================================================================
// K2/K4: vertical 32-tall box sum (running sum per column segment)
// ===========================================================================
template<int FINAL>
__global__ __launch_bounds__(256) void k_vbox(const float* __restrict__ im) {
    int idx = blockIdx.x * 256 + threadIdx.x;
    int x   = idx % IMW;
    int img = (idx / IMW) % NIMG;
    int seg = idx / (IMW * NIMG);
    int y0  = seg * 128;

    const float* col = g_tmp + img * IMH * IMW + x;
    float s = 0.0f;
    #pragma unroll
    for (int j = y0 - 16; j < y0 + 16; j++)
        if (j >= 0) s += col[j * IMW];

    const float* base = (FINAL ? (const float*)g_imc : im) + img * IMH * IMW + x;
    float* outp = g_imc + img * IMH * IMW + x;

    for (int y = y0; y < y0 + 128; y++) {
        if (y + 16 < IMH) s += col[(y + 16) * IMW];
        if (y - 16 >= 0)  s -= col[(y - 16) * IMW];
        float v = base[y * IMW];
        outp[y * IMW] = FINAL ? v / sqrtf(fmaxf(s, 0.0f))
                              : v - s * (1.0f / 1024.0f);
    }
}

// ===========================================================================
// K5: correlation via mma.sync (bf16 HMMA, family-portable on sm_103).
// Per row y': P[m,u] = sum_v a[y',x0+m+v-15]*T[u,v]  (M=128,N=32,K=32,
// 3-product bf16 split). Toeplitz A: all frags from 7 reg pairs/thread.
// P -> padded smem -> per-thread 32-deep register ring (thread = one x).
// Row buffer needs elements 0..158 (m+v max = 158) -> guards are i<159.
// Grid (4 x-strips, 2 y-halves, 48 imgs), 128 threads.
// ===========================================================================
#define PSTR 36   // P row stride in floats (conflict-free LDS.128 columns)

__device__ __forceinline__ void mma16816(float* c,
    uint32_t a0, uint32_t a1, uint32_t a2, uint32_t a3,
    uint32_t b0, uint32_t b1) {
    asm volatile(
        "mma.sync.aligned.m16n8k16.row.col.f32.bf16.bf16.f32 "
        "{%0,%1,%2,%3}, {%4,%5,%6,%7}, {%8,%9}, {%0,%1,%2,%3};"
        : "+f"(c[0]), "+f"(c[1]), "+f"(c[2]), "+f"(c[3])
        : "r"(a0), "r"(a1), "r"(a2), "r"(a3), "r"(b0), "r"(b1));
}

__device__ __forceinline__ void prep_store(__nv_bfloat16 (*rb)[160], int i, float v) {
    __nv_bfloat16 hi = __float2bfloat16(v);
    __nv_bfloat16 lo = __float2bfloat16(v - __bfloat162float(hi));
    rb[0][i] = hi;                    // hi, base
    rb[2][i] = lo;                    // lo, base
    if (i > 0) {
        rb[1][i-1] = hi;              // hi, shifted (sh[j] = buf[j+1])
        rb[3][i-1] = lo;              // lo, shifted
    }
}

__global__ __launch_bounds__(128) void k_conv_mma(float* __restrict__ out) {
    __shared__ float s_p[128][PSTR];                 // 18432 B
    __shared__ __nv_bfloat16 s_row[2][4][160];       // 2560 B  [buf][hiB,hiS,loB,loS]

    int tid  = threadIdx.x;
    int wid  = tid >> 5, lane = tid & 31;
    int g    = lane >> 2, tq = lane & 3;             // groupID, threadID-in-group
    int img  = blockIdx.z;
    int x0   = blockIdx.x * 128;
    int h    = blockIdx.y;

    int y0   = h ? 241 : 0;
    int yend = h ? 511 : 271;
    int olo  = h ? 256 : 0;

    const float* A = g_imc + (size_t)img * IMH * IMW;
    const float* T = g_tn + img * 1024;
    float* O = out + (size_t)img * IMH * IMW;

    // ---- B fragments (loop-invariant): Bh/Bl[kt][nt][2] ----
    uint32_t Bh[2][4][2], Bl[2][4][2];
    #pragma unroll
    for (int kt = 0; kt < 2; kt++)
        #pragma unroll
        for (int nt = 0; nt < 4; nt++) {
            int u = nt * 8 + g;
            #pragma unroll
            for (int hf = 0; hf < 2; hf++) {
                int v = kt * 16 + 2 * tq + hf * 8;
                float f0 = T[u * 32 + v], f1 = T[u * 32 + v + 1];
                __nv_bfloat16 h0 = __float2bfloat16(f0);
                __nv_bfloat16 h1 = __float2bfloat16(f1);
                __nv_bfloat162 ph; ph.x = h0; ph.y = h1;
                Bh[kt][nt][hf] = *(uint32_t*)&ph;
                __nv_bfloat162 pl;
                pl.x = __float2bfloat16(f0 - __bfloat162float(h0));
                pl.y = __float2bfloat16(f1 - __bfloat162float(h1));
                Bl[kt][nt][hf] = *(uint32_t*)&pl;
            }
        }

    // ---- zero row buffers, then load row y0 ----
    for (int i = tid; i < 2 * 4 * 160; i += 128)
        ((__nv_bfloat16*)s_row)[i] = __float2bfloat16(0.0f);
    __syncthreads();
    {
        float v0 = 0.f, v1 = 0.f;
        int i1 = tid + 128;
        int gx0 = x0 - 15 + tid, gx1 = x0 - 15 + i1;
        if (tid < 159 && (unsigned)gx0 < (unsigned)IMW) v0 = A[(size_t)y0 * IMW + gx0];
        if (i1  < 159 && (unsigned)gx1 < (unsigned)IMW) v1 = A[(size_t)y0 * IMW + gx1];
        if (tid < 159) prep_store(s_row[y0 & 1], tid, v0);
        if (i1  < 159) prep_store(s_row[y0 & 1], i1, v1);
    }

    float ring[32];
    #pragma unroll
    for (int i = 0; i < 32; i++) ring[i] = 0.f;

    int pbase = wid * 32 + g + 2 * tq;   // Toeplitz base index for this thread
    int par   = g & 1;                   // parity -> choose shifted arrays
    int eidx  = pbase - par;             // even, b32-aligned element index

    #pragma unroll 1
    for (int yp = y0; yp <= yend; yp++) {
        // prefetch next row (LDG early, store later)
        float v0 = 0.f, v1 = 0.f;
        int np = yp + 1;
        int i1 = tid + 128;
        if (np <= yend) {
            int gx0 = x0 - 15 + tid, gx1 = x0 - 15 + i1;
            if (tid < 159 && (unsigned)gx0 < (unsigned)IMW) v0 = A[(size_t)np * IMW + gx0];
            if (i1  < 159 && (unsigned)gx1 < (unsigned)IMW) v1 = A[(size_t)np * IMW + gx1];
        }

        __syncthreads();  // P free (prev reads done); s_row[yp&1] ready

        // A fragments: 7 even-aligned b32 pairs per split
        const __nv_bfloat16* bh = &s_row[yp & 1][par ? 1 : 0][0];
        const __nv_bfloat16* bl = &s_row[yp & 1][par ? 3 : 2][0];
        uint32_t wh[7], wl[7];
        #pragma unroll
        for (int q = 0; q < 7; q++) {
            wh[q] = *(const uint32_t*)(bh + eidx + 8 * q);
            wl[q] = *(const uint32_t*)(bl + eidx + 8 * q);
        }

        float acc[2][4][4];
        #pragma unroll
        for (int mt = 0; mt < 2; mt++)
            #pragma unroll
            for (int nt = 0; nt < 4; nt++)
                #pragma unroll
                for (int k = 0; k < 4; k++) acc[mt][nt][k] = 0.f;

        #pragma unroll
        for (int kt = 0; kt < 2; kt++)
            #pragma unroll
            for (int mt = 0; mt < 2; mt++) {
                int q = 2 * (mt + kt);
                #pragma unroll
                for (int nt = 0; nt < 4; nt++) {
                    mma16816(acc[mt][nt], wh[q], wh[q+1], wh[q+1], wh[q+2],
                             Bh[kt][nt][0], Bh[kt][nt][1]);
                    mma16816(acc[mt][nt], wh[q], wh[q+1], wh[q+1], wh[q+2],
                             Bl[kt][nt][0], Bl[kt][nt][1]);
                    mma16816(acc[mt][nt], wl[q], wl[q+1], wl[q+1], wl[q+2],
                             Bh[kt][nt][0], Bh[kt][nt][1]);
                }
            }

        // D fragments -> padded P buffer
        #pragma unroll
        for (int mt = 0; mt < 2; mt++) {
            int xr = wid * 32 + mt * 16 + g;
            #pragma unroll
            for (int nt = 0; nt < 4; nt++) {
                int u = nt * 8 + 2 * tq;
                *(float2*)&s_p[xr][u]     = make_float2(acc[mt][nt][0], acc[mt][nt][1]);
                *(float2*)&s_p[xr + 8][u] = make_float2(acc[mt][nt][2], acc[mt][nt][3]);
            }
        }

        // store prefetched row into the other buffer
        if (np <= yend) {
            if (tid < 159) prep_store(s_row[np & 1], tid, v0);
            if (i1  < 159) prep_store(s_row[np & 1], i1, v1);
        }
        __syncthreads();

        // column read: thread = one x, all 32 u; ring combine
        #pragma unroll
        for (int j = 0; j < 8; j++) {
            float4 pv = *(float4*)&s_p[tid][4 * j];
            ring[31 - (4*j    )] += pv.x;
            ring[31 - (4*j + 1)] += pv.y;
            ring[31 - (4*j + 2)] += pv.z;
            ring[31 - (4*j + 3)] += pv.w;
        }
        int orow = yp - 16;
        if (orow >= olo)
            O[(size_t)orow * IMW + x0 + tid] = ring[0];
        #pragma unroll
        for (int i = 0; i < 31; i++) ring[i] = ring[i + 1];
        ring[31] = 0.f;
    }

    if (h == 1) {
        #pragma unroll
        for (int i = 0; i < 16; i++)
            O[(size_t)(496 + i) * IMW + x0 + tid] = ring[i];
    }
}

// ===========================================================================
extern "C" void kernel_launch(void* const* d_in, const int* in_sizes, int n_in,
                              void* d_out, int out_size) {
    const float* im   = (const float*)d_in[0];  // (16,3,512,512) f32
    const float* tmpl = (const float*)d_in[1];  // (16,3,32,32)  f32
    float* out = (float*)d_out;                 // (16,3,512,512) f32

    k_tnorm<<<NIMG, 256>>>(tmpl);
    k_hbox<0><<<NIMG * IMH / 8, 256>>>(im);                 // S1 horizontal
    k_vbox<0><<<NIMG * IMW * 4 / 256, 256>>>(im);           // im_c
    k_hbox<1><<<NIMG * IMH / 8, 256>>>(im);                 // S2 horizontal (imc^2)
    k_vbox<1><<<NIMG * IMW * 4 / 256, 256>>>(im);           // a = imc/energy
    k_conv_mma<<<dim3(4, 2, NIMG), 128>>>(out);             // HMMA correlation
}

// round 17
// speedup vs baseline: 1.3073x; 1.0800x over previous
#include <cuda_runtime.h>
#include <cuda_bf16.h>
#include <cstdint>

#define IMW 512
#define IMH 512
#define NIMG 48          // B*C = 16*3
#define TSZ 32

// Scratch (static __device__ — no allocations allowed)
__device__ float g_tmp[NIMG*IMH*IMW];
__device__ float g_imc[NIMG*IMH*IMW];
__device__ float g_tn [NIMG*TSZ*TSZ];

// ===========================================================================
// K0: template normalize: tn = (t - mean) / ||t - mean||
// ===========================================================================
__global__ void k_tnorm(const float* __restrict__ t) {
    __shared__ float red[256];
    int img = blockIdx.x;
    int tid = threadIdx.x;
    const float4* tp = (const float4*)(t + img * 1024);
    float4 v = tp[tid];
    red[tid] = v.x + v.y + v.z + v.w;
    __syncthreads();
    for (int o = 128; o > 0; o >>= 1) {
        if (tid < o) red[tid] += red[tid + o];
        __syncthreads();
    }
    float mean = red[0] * (1.0f / 1024.0f);
    __syncthreads();
    float cx = v.x - mean, cy = v.y - mean, cz = v.z - mean, cw = v.w - mean;
    red[tid] = cx*cx + cy*cy + cz*cz + cw*cw;
    __syncthreads();
    for (int o = 128; o > 0; o >>= 1) {
        if (tid < o) red[tid] += red[tid + o];
        __syncthreads();
    }
    float inv = 1.0f / sqrtf(red[0]);
    float4* outp = (float4*)(g_tn + img * 1024);
    outp[tid] = make_float4(cx*inv, cy*inv, cz*inv, cw*inv);
}

// ===========================================================================
// K1/K3: horizontal 32-wide box sum (running sum, bank-skewed smem)
// ===========================================================================
#define HP(c) ((c) + ((c) >> 4))

template<int SQ>
__global__ __launch_bounds__(256) void k_hbox(const float* __restrict__ im) {
    __shared__ float s [8][578];
    __shared__ float so[8][544];
    int tid = threadIdx.x;
    int row0 = blockIdx.x * 8;
    const float* src = SQ ? (const float*)g_imc : im;

    for (int i = tid; i < 8 * 544; i += 256) {
        int r = i / 544, c = i % 544;
        float v = 0.0f;
        if (c >= 16 && c < 528) {
            v = src[(row0 + r) * IMW + (c - 16)];
            if (SQ) v *= v;
        }
        s[r][HP(c)] = v;
    }
    __syncthreads();

    int w = tid >> 5, lane = tid & 31;
    int x0 = lane * 16;
    float sum = 0.0f;
    #pragma unroll
    for (int j = 0; j < 32; j++) sum += s[w][HP(x0 + 1 + j)];
    so[w][HP(x0)] = sum;
    #pragma unroll
    for (int i = 1; i < 16; i++) {
        sum += s[w][HP(x0 + 32 + i)] - s[w][HP(x0 + i)];
        so[w][HP(x0 + i)] = sum;
    }
    __syncthreads();

    for (int i = tid; i < 8 * 512; i += 256) {
        int r = i >> 9, c = i & 511;
        g_tmp[(row0 + r) * IMW + c] = so[r][HP(c)];
    }
}

// ===========================================================================
// K2/K4: vertical 32-tall box sum (running sum per column segment)
// ===========================================================================
template<int FINAL>
__global__ __launch_bounds__(256) void k_vbox(const float* __restrict__ im) {
    int idx = blockIdx.x * 256 + threadIdx.x;
    int x   = idx % IMW;
    int img = (idx / IMW) % NIMG;
    int seg = idx / (IMW * NIMG);
    int y0  = seg * 128;

    const float* col = g_tmp + img * IMH * IMW + x;
    float s = 0.0f;
    #pragma unroll
    for (int j = y0 - 16; j < y0 + 16; j++)
        if (j >= 0) s += col[j * IMW];

    const float* base = (FINAL ? (const float*)g_imc : im) + img * IMH * IMW + x;
    float* outp = g_imc + img * IMH * IMW + x;

    for (int y = y0; y < y0 + 128; y++) {
        if (y + 16 < IMH) s += col[(y + 16) * IMW];
        if (y - 16 >= 0)  s -= col[(y - 16) * IMW];
        float v = base[y * IMW];
        outp[y * IMW] = FINAL ? v / sqrtf(fmaxf(s, 0.0f))
                              : v - s * (1.0f / 1024.0f);
    }
}

// ===========================================================================
// K5: correlation via mma.sync (bf16 HMMA). Pipelined version:
//  - row smem triple-buffered, LDG prefetch distance 2
//  - P double-buffered + combine lagged one row -> ONE barrier per row
//  - P stored transposed s_pT[u][x] (stride 132) -> conflict-free STS & LDS
// Grid (4 x-strips, 2 y-halves, 48 imgs), 128 threads.
// ===========================================================================
#define PSTRT 132   // P transposed row stride in floats

__device__ __forceinline__ void mma16816(float* c,
    uint32_t a0, uint32_t a1, uint32_t a2, uint32_t a3,
    uint32_t b0, uint32_t b1) {
    asm volatile(
        "mma.sync.aligned.m16n8k16.row.col.f32.bf16.bf16.f32 "
        "{%0,%1,%2,%3}, {%4,%5,%6,%7}, {%8,%9}, {%0,%1,%2,%3};"
        : "+f"(c[0]), "+f"(c[1]), "+f"(c[2]), "+f"(c[3])
        : "r"(a0), "r"(a1), "r"(a2), "r"(a3), "r"(b0), "r"(b1));
}

__device__ __forceinline__ void prep_store(__nv_bfloat16 (*rb)[160], int i, float v) {
    __nv_bfloat16 hi = __float2bfloat16(v);
    __nv_bfloat16 lo = __float2bfloat16(v - __bfloat162float(hi));
    rb[0][i] = hi;                    // hi, base
    rb[2][i] = lo;                    // lo, base
    if (i > 0) {
        rb[1][i-1] = hi;              // hi, shifted (sh[j] = buf[j+1])
        rb[3][i-1] = lo;              // lo, shifted
    }
}

__global__ __launch_bounds__(128) void k_conv_mma(float* __restrict__ out) {
    __shared__ float s_pT[2][32][PSTRT];             // 33792 B (transposed P)
    __shared__ __nv_bfloat16 s_row[3][4][160];       // 3840 B

    int tid  = threadIdx.x;
    int wid  = tid >> 5, lane = tid & 31;
    int g    = lane >> 2, tq = lane & 3;             // groupID, threadID-in-group
    int img  = blockIdx.z;
    int x0   = blockIdx.x * 128;
    int h    = blockIdx.y;

    int y0   = h ? 241 : 0;
    int yend = h ? 511 : 271;
    int olo  = h ? 256 : 0;

    const float* A = g_imc + (size_t)img * IMH * IMW;
    const float* T = g_tn + img * 1024;
    float* O = out + (size_t)img * IMH * IMW;

    // ---- B fragments (loop-invariant): Bh/Bl[kt][nt][2] ----
    uint32_t Bh[2][4][2], Bl[2][4][2];
    #pragma unroll
    for (int kt = 0; kt < 2; kt++)
        #pragma unroll
        for (int nt = 0; nt < 4; nt++) {
            int u = nt * 8 + g;
            #pragma unroll
            for (int hf = 0; hf < 2; hf++) {
                int v = kt * 16 + 2 * tq + hf * 8;
                float f0 = T[u * 32 + v], f1 = T[u * 32 + v + 1];
                __nv_bfloat16 h0 = __float2bfloat16(f0);
                __nv_bfloat16 h1 = __float2bfloat16(f1);
                __nv_bfloat162 ph; ph.x = h0; ph.y = h1;
                Bh[kt][nt][hf] = *(uint32_t*)&ph;
                __nv_bfloat162 pl;
                pl.x = __float2bfloat16(f0 - __bfloat162float(h0));
                pl.y = __float2bfloat16(f1 - __bfloat162float(h1));
                Bl[kt][nt][hf] = *(uint32_t*)&pl;
            }
        }

    // ---- zero row buffers, then load rows y0, y0+1 ----
    for (int i = tid; i < 3 * 4 * 160; i += 128)
        ((__nv_bfloat16*)s_row)[i] = __float2bfloat16(0.0f);
    __syncthreads();
    {
        int i1 = tid + 128;
        int gx0 = x0 - 15 + tid, gx1 = x0 - 15 + i1;
        #pragma unroll
        for (int pr = 0; pr < 2; pr++) {
            int yr = y0 + pr;
            float v0 = 0.f, v1 = 0.f;
            if (tid < 159 && (unsigned)gx0 < (unsigned)IMW) v0 = A[(size_t)yr * IMW + gx0];
            if (i1  < 159 && (unsigned)gx1 < (unsigned)IMW) v1 = A[(size_t)yr * IMW + gx1];
            if (tid < 159) prep_store(s_row[yr % 3], tid, v0);
            if (i1  < 159) prep_store(s_row[yr % 3], i1, v1);
        }
    }
    __syncthreads();

    float ring[32];
    #pragma unroll
    for (int i = 0; i < 32; i++) ring[i] = 0.f;

    int pbase = wid * 32 + g + 2 * tq;   // Toeplitz base index for this thread
    int par   = g & 1;                   // parity -> choose shifted arrays
    int eidx  = pbase - par;             // even, b32-aligned element index

    #pragma unroll 1
    for (int yp = y0; yp <= yend; yp++) {
        // prefetch row yp+2 (LDG early; lands over a full iteration)
        float v0 = 0.f, v1 = 0.f;
        int np = yp + 2;
        int i1 = tid + 128;
        if (np <= yend) {
            int gx0 = x0 - 15 + tid, gx1 = x0 - 15 + i1;
            if (tid < 159 && (unsigned)gx0 < (unsigned)IMW) v0 = A[(size_t)np * IMW + gx0];
            if (i1  < 159 && (unsigned)gx1 < (unsigned)IMW) v1 = A[(size_t)np * IMW + gx1];
        }

        // A fragments from s_row[yp%3] (written 2 iters ago)
        int rb = yp % 3;
        const __nv_bfloat16* bh = &s_row[rb][par ? 1 : 0][0];
        const __nv_bfloat16* bl = &s_row[rb][par ? 3 : 2][0];
        uint32_t wh[7], wl[7];
        #pragma unroll
        for (int q = 0; q < 7; q++) {
            wh[q] = *(const uint32_t*)(bh + eidx + 8 * q);
            wl[q] = *(const uint32_t*)(bl + eidx + 8 * q);
        }

        float acc[2][4][4];
        #pragma unroll
        for (int mt = 0; mt < 2; mt++)
            #pragma unroll
            for (int nt = 0; nt < 4; nt++)
                #pragma unroll
                for (int k = 0; k < 4; k++) acc[mt][nt][k] = 0.f;

        #pragma unroll
        for (int kt = 0; kt < 2; kt++)
            #pragma unroll
            for (int mt = 0; mt < 2; mt++) {
                int q = 2 * (mt + kt);
                #pragma unroll
                for (int nt = 0; nt < 4; nt++) {
                    mma16816(acc[mt][nt], wh[q], wh[q+1], wh[q+1], wh[q+2],
                             Bh[kt][nt][0], Bh[kt][nt][1]);
                    mma16816(acc[mt][nt], wh[q], wh[q+1], wh[q+1], wh[q+2],
                             Bl[kt][nt][0], Bl[kt][nt][1]);
                    mma16816(acc[mt][nt], wl[q], wl[q+1], wl[q+1], wl[q+2],
                             Bh[kt][nt][0], Bh[kt][nt][1]);
                }
            }

        // D fragments -> transposed P buffer (conflict-free scalar STS)
        int pb = yp & 1;
        #pragma unroll
        for (int mt = 0; mt < 2; mt++) {
            int xr = wid * 32 + mt * 16 + g;
            #pragma unroll
            for (int nt = 0; nt < 4; nt++) {
                int u0 = nt * 8 + 2 * tq;
                s_pT[pb][u0    ][xr]     = acc[mt][nt][0];
                s_pT[pb][u0 + 1][xr]     = acc[mt][nt][1];
                s_pT[pb][u0    ][xr + 8] = acc[mt][nt][2];
                s_pT[pb][u0 + 1][xr + 8] = acc[mt][nt][3];
            }
        }

        // store prefetched row into buffer (yp+2) % 3
        if (np <= yend) {
            if (tid < 159) prep_store(s_row[np % 3], tid, v0);
            if (i1  < 159) prep_store(s_row[np % 3], i1, v1);
        }

        // combine PREVIOUS row's P (lagged by 1) — conflict-free column read
        if (yp > y0) {
            int qb = (yp - 1) & 1;
            #pragma unroll
            for (int u = 0; u < 32; u++)
                ring[31 - u] += s_pT[qb][u][tid];
            int orow = yp - 17;
            if (orow >= olo)
                O[(size_t)orow * IMW + x0 + tid] = ring[0];
            #pragma unroll
            for (int i = 0; i < 31; i++) ring[i] = ring[i + 1];
            ring[31] = 0.f;
        }

        __syncthreads();
    }

    // epilogue: combine row yend
    {
        int qb = yend & 1;
        #pragma unroll
        for (int u = 0; u < 32; u++)
            ring[31 - u] += s_pT[qb][u][tid];
        int orow = yend - 16;
        if (orow >= olo)
            O[(size_t)orow * IMW + x0 + tid] = ring[0];
        #pragma unroll
        for (int i = 0; i < 31; i++) ring[i] = ring[i + 1];
        ring[31] = 0.f;
    }

    if (h == 1) {
        #pragma unroll
        for (int i = 0; i < 16; i++)
            O[(size_t)(496 + i) * IMW + x0 + tid] = ring[i];
    }
}

// ===========================================================================
extern "C" void kernel_launch(void* const* d_in, const int* in_sizes, int n_in,
                              void* d_out, int out_size) {
    const float* im   = (const float*)d_in[0];  // (16,3,512,512) f32
    const float* tmpl = (const float*)d_in[1];  // (16,3,32,32)  f32
    float* out = (float*)d_out;                 // (16,3,512,512) f32

    k_tnorm<<<NIMG, 256>>>(tmpl);
    k_hbox<0><<<NIMG * IMH / 8, 256>>>(im);                 // S1 horizontal
    k_vbox<0><<<NIMG * IMW * 4 / 256, 256>>>(im);           // im_c
    k_hbox<1><<<NIMG * IMH / 8, 256>>>(im);                 // S2 horizontal (imc^2)
    k_vbox<1><<<NIMG * IMW * 4 / 256, 256>>>(im);           // a = imc/energy
    k_conv_mma<<<dim3(4, 2, NIMG), 128>>>(out);             // HMMA correlation
}